// round 9
// baseline (speedup 1.0000x reference)
#include <cuda_runtime.h>
#include <cuda_fp16.h>
#include <cstdint>

// Problem constants: B=4, N=512, F=FE=FG=MID=OUT=128
#define BB 4
#define NN 512
#define CC 128
#define AS_STRIDE 132
#define RET_ELEMS (BB*NN*CC)          // 262144
#define NIB 8                         // i-blocks of 64 (512/64)

// ---------------- device scratch ----------------
__device__ float g_m1g [BB*NN*CC];              // node@w1+b1 (msgg added at final stage)
__device__ float g_msg2[BB*NN*CC];
__device__ float g_h1  [BB*NN*CC];
__device__ float g_msgg[BB*CC];
__device__ unsigned g_red[BB*NN*CC];            // encoded running max (1 MB)
__device__ int   g_cnt[BB*32];                  // per-(b,jt) arrival counters
__device__ int   g_adjflag;
__device__ __half g_wf16[CC*CC];                // W [k][n] fp16

// ---------------- helpers ----------------
__device__ __forceinline__ uint32_t smem_to_u32(const void* p) {
    uint32_t a;
    asm("{ .reg .u64 t; cvta.to.shared.u64 t, %1; cvt.u32.u64 %0, t; }"
        : "=r"(a) : "l"(p));
    return a;
}
__device__ __forceinline__ void ldsm_x4(uint32_t (&r)[4], uint32_t addr) {
    asm volatile("ldmatrix.sync.aligned.m8n8.x4.shared.b16 {%0,%1,%2,%3}, [%4];"
                 : "=r"(r[0]), "=r"(r[1]), "=r"(r[2]), "=r"(r[3]) : "r"(addr));
}
__device__ __forceinline__ void ldsm_x4_t(uint32_t (&r)[4], uint32_t addr) {
    asm volatile("ldmatrix.sync.aligned.m8n8.x4.trans.shared.b16 {%0,%1,%2,%3}, [%4];"
                 : "=r"(r[0]), "=r"(r[1]), "=r"(r[2]), "=r"(r[3]) : "r"(addr));
}
__device__ __forceinline__ void mma_f16(float (&d)[4], const uint32_t (&a)[4],
                                        uint32_t b0, uint32_t b1) {
    asm volatile("mma.sync.aligned.m16n8k16.row.col.f32.f16.f16.f32 "
                 "{%0,%1,%2,%3}, {%4,%5,%6,%7}, {%8,%9}, {%0,%1,%2,%3};"
                 : "+f"(d[0]), "+f"(d[1]), "+f"(d[2]), "+f"(d[3])
                 : "r"(a[0]), "r"(a[1]), "r"(a[2]), "r"(a[3]), "r"(b0), "r"(b1));
}
// order-preserving float<->uint for atomicMax
__device__ __forceinline__ unsigned encf(float f) {
    unsigned u = __float_as_uint(f);
    return (u & 0x80000000u) ? ~u : (u | 0x80000000u);
}
__device__ __forceinline__ float decf(unsigned u) {
    return __uint_as_float((u & 0x80000000u) ? (u & 0x7FFFFFFFu) : ~u);
}
__device__ __forceinline__ unsigned long long fma2(unsigned long long a,
                                                   unsigned long long b,
                                                   unsigned long long c) {
    unsigned long long d;
    asm("fma.rn.f32x2 %0, %1, %2, %3;" : "=l"(d) : "l"(a), "l"(b), "l"(c));
    return d;
}
__device__ __forceinline__ unsigned long long pack2(float x) {
    unsigned long long d;
    asm("mov.b64 %0, {%1, %1};" : "=l"(d) : "f"(x));
    return d;
}
__device__ __forceinline__ float2 unpack2(unsigned long long v) {
    float2 f;
    asm("mov.b64 {%0, %1}, %2;" : "=f"(f.x), "=f"(f.y) : "l"(v));
    return f;
}

// 64-row fp32x2 GEMM core (proj blocks inside setup)
__device__ __forceinline__ void gemm_core64(const float* __restrict__ As,
                                            const float* __restrict__ Ws,
                                            unsigned long long acc[4][4],
                                            int tx, int ty)
{
    const float* a0 = As + ty * 4 * AS_STRIDE;
    const float* w0 = Ws + tx * 8;
#pragma unroll 4
    for (int k = 0; k < CC; k++) {
        const ulonglong2 q0 = *(const ulonglong2*)(w0 + k * CC);
        const ulonglong2 q1 = *(const ulonglong2*)(w0 + k * CC + 4);
        const unsigned long long b0 = q0.x, b1 = q0.y, b2 = q1.x, b3 = q1.y;
#pragma unroll
        for (int r = 0; r < 4; r++) {
            const unsigned long long ap = pack2(a0[r * AS_STRIDE + k]);
            acc[r][0] = fma2(ap, b0, acc[r][0]);
            acc[r][1] = fma2(ap, b1, acc[r][1]);
            acc[r][2] = fma2(ap, b2, acc[r][2]);
            acc[r][3] = fma2(ap, b3, acc[r][3]);
        }
    }
}

// ---------------- noop: keeps launch count/order stable for profiling ----------------
__global__ void noop_kernel() {}

// ================ merged setup kernel (setup + node projections) ================
// blk 0: adj detect + counter zero; 1..64: W fp16 prep; 65..68: msg_g;
// 69..132: g_red init; 133..228: proj GEMMs (96 blocks: 32 row-tiles of 64 x 3 sets)
__global__ __launch_bounds__(256) void setup_kernel(
    const void* __restrict__ adj, const float* __restrict__ w_me,
    const float* __restrict__ graph, const float* __restrict__ w_mg,
    const float* __restrict__ b_mg,
    const float* __restrict__ node,
    const float* __restrict__ w1, const float* __restrict__ bb1,
    const float* __restrict__ w2, const float* __restrict__ bb2,
    const float* __restrict__ w3, const float* __restrict__ bb3)
{
    const int blk = blockIdx.x;
    const int t = threadIdx.x;
    if (blk == 0) {
        __shared__ int cnt[3];
        if (t < 3) cnt[t] = 0;
        if (t < 128) g_cnt[t] = 0;                        // zero arrival counters
        __syncthreads();
#pragma unroll
        for (int u = 0; u < 2; u++) {
            size_t d = (size_t)(t + 256 * u) * 513;       // batch-0 diagonal, < 1 MB
            if (((const unsigned char*)adj)[d] == 1) atomicAdd(&cnt[0], 1);
            if (((const int*)adj)[d] == 1)           atomicAdd(&cnt[1], 1);
            if (((const float*)adj)[d] == 1.0f)      atomicAdd(&cnt[2], 1);
        }
        __syncthreads();
        if (t == 0) {
            int f = 0;
            if (cnt[0] == 512) f = 0;
            else if (cnt[1] == 512) f = 1;
            else if (cnt[2] == 512) f = 2;
            g_adjflag = f;
        }
    } else if (blk <= 64) {
        int idx = (blk - 1) * 256 + t;                    // 16384 total
        g_wf16[idx] = __float2half_rn(w_me[idx]);
    } else if (blk <= 68) {
        const int b = blk - 65;
        __shared__ float gr[CC];
        if (t < CC) gr[t] = graph[b * CC + t];
        __syncthreads();
        if (t < CC) {
            float acc = b_mg[t];
#pragma unroll 8
            for (int k = 0; k < CC; k++)
                acc = fmaf(gr[k], w_mg[k * CC + t], acc);
            g_msgg[b * CC + t] = acc;
        }
    } else if (blk <= 132) {
        const unsigned NEGU = encf(-3.0e38f);
        uint4 v = make_uint4(NEGU, NEGU, NEGU, NEGU);
        uint4* dst = (uint4*)g_red + (size_t)(blk - 69) * 1024 + t * 4;
#pragma unroll
        for (int q = 0; q < 4; q++) dst[q] = v;
    } else {
        // ---- proj: blocks 133..228, 64-row tiles ----
        extern __shared__ char smem[];
        float* Ws = (float*)smem;
        float* As = Ws + CC * CC;
        const int pidx = blk - 133;
        const int y  = pidx >> 5;          // 0..2 weight set
        const int px = pidx & 31;          // row tile (64 rows)
        const int tx = t & 15, ty = t >> 4;
        const float* W    = (y == 0) ? w1  : ((y == 1) ? w2  : w3);
        const float* bias = (y == 0) ? bb1 : ((y == 1) ? bb2 : bb3);
        float* out        = (y == 0) ? g_m1g : ((y == 1) ? g_msg2 : g_h1);
        const int rbase = px * 64;

        for (int m = t; m < 4096; m += 256)
            *(float4*)(Ws + m * 4) = *(const float4*)(W + m * 4);
        for (int m = t; m < 2048; m += 256) {
            int rr = m >> 5, kk = (m & 31) << 2;
            *(float4*)(As + rr * AS_STRIDE + kk) =
                *(const float4*)(node + (size_t)(rbase + rr) * CC + kk);
        }
        __syncthreads();

        unsigned long long acc[4][4];
#pragma unroll
        for (int r = 0; r < 4; r++)
#pragma unroll
            for (int p = 0; p < 4; p++) acc[r][p] = 0ull;
        gemm_core64(As, Ws, acc, tx, ty);

        float addv[8];
        *(float4*)(addv)     = *(const float4*)(bias + tx * 8);
        *(float4*)(addv + 4) = *(const float4*)(bias + tx * 8 + 4);
#pragma unroll
        for (int r = 0; r < 4; r++) {
            int row = rbase + ty * 4 + r;
            float v[8];
#pragma unroll
            for (int p = 0; p < 4; p++) {
                float2 f = unpack2(acc[r][p]);
                v[2 * p]     = f.x + addv[2 * p];
                v[2 * p + 1] = f.y + addv[2 * p + 1];
            }
            float* op = out + (size_t)row * CC + tx * 8;
            *(float4*)op       = make_float4(v[0], v[1], v[2], v[3]);
            *(float4*)(op + 4) = make_float4(v[4], v[5], v[6], v[7]);
        }
    }
}

// ======== big fused kernel: fp16 HMMA GEMM + masked max + fused final (last CTA) ========
// grid (32 j-tiles of 16, 8 i-blocks of 64, 4 batches), 256 threads (8 warps 2Mx4N).
#define ROWSTRIDE 272                 // (128+8)*2 bytes, conflict-free LDSM
#define SM_W    0                     // 128 x 272 fp16 W image (34816)
#define SM_A    (SM_W   + 128*ROWSTRIDE)      // 128 x 272 fp16 A image
#define SM_MSG2 (SM_A   + 128*ROWSTRIDE)      // 64 x 128 fp32 = 32768
#define SM_PMU  (SM_MSG2 + 64*CC*4)           // 16 x 128 uint = 8192
#define SM_ADJ  (SM_PMU + 16*CC*4)            // 64 x 16 = 1024 (reused as flag later)
#define SM_BIAS (SM_ADJ + 1024)               // 128 fp32
#define SMEM_BIG_T (SM_BIAS + 512)            // 112,128 bytes -> 2 CTAs/SM
// fused-final reuse (after all other smem uses are dead):
#define SM_WO2  0                             // 16384 fp32 = 65536 B
#define SM_AS2  66560                         // 16 x AS_STRIDE fp32 = 8448 B

__global__ __launch_bounds__(256, 2) void big_kernel(
    const float* __restrict__ edge, const void* __restrict__ adj,
    const float* __restrict__ b_me,
    const float* __restrict__ w_o2, const float* __restrict__ b_o2,
    float* __restrict__ out_ret, float* __restrict__ out_me)
{
    extern __shared__ char smem[];
    const int tid  = threadIdx.x;
    const int lane = tid & 31;
    const int wid  = tid >> 5;
    const int warp_m = wid >> 2;      // 0..1  (64 rows each)
    const int warp_n = wid & 3;       // 0..3  (32 cols each)
    const int jt = blockIdx.x, iblk = blockIdx.y, b = blockIdx.z;
    const int j0 = jt * 16, ibase = iblk * 64;
    const uint32_t sb = smem_to_u32(smem);

    // ---- resident loads ----
    {
        for (int m = tid; m < 2048; m += 256) {            // W fp16 padded image
            int row = m >> 4, q = m & 15;
            *(uint4*)(smem + SM_W + row * ROWSTRIDE + q * 16) =
                ((const uint4*)g_wf16)[row * 16 + q];
        }
        const float4* m2src = (const float4*)(g_msg2 + (((size_t)b * NN + ibase) * CC));
        float4* m2dst = (float4*)(smem + SM_MSG2);
#pragma unroll
        for (int q = 0; q < 8; q++) m2dst[tid + 256 * q] = m2src[tid + 256 * q];

        if (tid < 64) {
            const int flag = g_adjflag;
            const size_t rowoff = (((size_t)b * NN) + ibase + tid) * NN + j0;
            unsigned char* dst = (unsigned char*)(smem + SM_ADJ) + tid * 16;
            if (flag == 0) {
                *(uint4*)dst = *(const uint4*)((const unsigned char*)adj + rowoff);
            } else if (flag == 1) {
                const int* p = (const int*)adj + rowoff;
#pragma unroll
                for (int q = 0; q < 16; q++) dst[q] = (p[q] != 0);
            } else {
                const float* p = (const float*)adj + rowoff;
#pragma unroll
                for (int q = 0; q < 16; q++) dst[q] = (p[q] != 0.0f);
            }
        }
        if (tid < 128) ((float*)(smem + SM_BIAS))[tid] = b_me[tid];
        const unsigned NEGU = encf(-3.0e38f);
        for (int m = tid; m < 2048; m += 256) ((unsigned*)(smem + SM_PMU))[m] = NEGU;
    }

    const float* m2S = (const float*)(smem + SM_MSG2);
    const unsigned char* adjS = (const unsigned char*)(smem + SM_ADJ);
    unsigned* pmu = (unsigned*)(smem + SM_PMU);

    const uint32_t lm_off = (uint32_t)((lane & 15) * ROWSTRIDE + (lane >> 4) * 16);
    const uint32_t a_warp = (uint32_t)(warp_m * 64 * ROWSTRIDE);
    const uint32_t b_warp = (uint32_t)(warp_n * 64);   // 32 cols * 2B

    const int jlA = lane >> 2, jlB = jlA + 8;
    float bc[4][2];
#pragma unroll
    for (int ni = 0; ni < 4; ni++) {
        int c0 = warp_n * 32 + ni * 8 + (lane & 3) * 2;
        bc[ni][0] = b_me[c0]; bc[ni][1] = b_me[c0 + 1];
    }
    __syncthreads();

    float4 ld[4];   // quarter prefetch of next sub-tile

    for (int sub = 0; sub < 8; sub++) {
        const float4* ebase = (const float4*)(edge +
            (((size_t)b * NN + ibase + sub * 8) * NN + j0) * CC);
        const int it0 = (sub == 0) ? 0 : 4;
        if (sub > 0) {
#pragma unroll
            for (int it = 0; it < 4; it++) {
                int m = tid + it * 256;
                int row = m >> 5, c4 = m & 31;
                float4 f = ld[it];
                __half2 hp0(__float2half_rn(f.x), __float2half_rn(f.y));
                __half2 hp1(__float2half_rn(f.z), __float2half_rn(f.w));
                *(uint2*)(smem + SM_A + row * ROWSTRIDE + c4 * 8) =
                    make_uint2(*(uint32_t*)&hp0, *(uint32_t*)&hp1);
            }
        }
#pragma unroll 4
        for (int it = it0; it < 16; it++) {
            int m = tid + it * 256;
            int row = m >> 5, c4 = m & 31;       // row = il*16+jl
            int il = row >> 4, jl = row & 15;
            float4 f = ebase[((size_t)il * NN + jl) * 32 + c4];
            __half2 hp0(__float2half_rn(f.x), __float2half_rn(f.y));
            __half2 hp1(__float2half_rn(f.z), __float2half_rn(f.w));
            *(uint2*)(smem + SM_A + row * ROWSTRIDE + c4 * 8) =
                make_uint2(*(uint32_t*)&hp0, *(uint32_t*)&hp1);
        }
        __syncthreads();

        if (sub < 7) {
            const float4* enext = (const float4*)(edge +
                (((size_t)b * NN + ibase + (sub + 1) * 8) * NN + j0) * CC);
#pragma unroll
            for (int it = 0; it < 4; it++) {
                int m = tid + it * 256;
                int row = m >> 5, c4 = m & 31;
                int il = row >> 4, jl = row & 15;
                ld[it] = enext[((size_t)il * NN + jl) * 32 + c4];
            }
        }

        // ---- single-pass fp16 HMMA ----
        float acc[4][4][4];
#pragma unroll
        for (int mi = 0; mi < 4; mi++)
#pragma unroll
            for (int ni = 0; ni < 4; ni++)
#pragma unroll
                for (int q = 0; q < 4; q++) acc[mi][ni][q] = 0.0f;

        const uint32_t abase = sb + SM_A + a_warp + lm_off;
        const uint32_t bbase = sb + SM_W + b_warp + lm_off;
#pragma unroll
        for (int ks = 0; ks < 8; ks++) {
            uint32_t af[4][4];
            uint32_t bf[2][4];
#pragma unroll
            for (int mi = 0; mi < 4; mi++)
                ldsm_x4(af[mi], abase + mi * 16 * ROWSTRIDE + ks * 32);
#pragma unroll
            for (int nh = 0; nh < 2; nh++)
                ldsm_x4_t(bf[nh], bbase + ks * 16 * ROWSTRIDE + nh * 32);
#pragma unroll
            for (int mi = 0; mi < 4; mi++) {
#pragma unroll
                for (int ni = 0; ni < 4; ni++)
                    mma_f16(acc[mi][ni], af[mi],
                            bf[ni >> 1][(ni & 1) * 2], bf[ni >> 1][(ni & 1) * 2 + 1]);
            }
        }

        // ---- epilogue: bias + STG + masked smem atomicMax ----
#pragma unroll
        for (int mi = 0; mi < 4; mi++) {
            const int il = warp_m * 4 + mi;
            const int ii = sub * 8 + il;
            const bool aA = adjS[ii * 16 + jlA] != 0;
            const bool aB = adjS[ii * 16 + jlB] != 0;
            const float* m2row = m2S + ii * CC;
            float* rowA = out_me + (((size_t)b * NN + ibase + ii) * NN + j0 + jlA) * CC;
            float* rowB = rowA + 8 * CC;
#pragma unroll
            for (int ni = 0; ni < 4; ni++) {
                const int c0 = warp_n * 32 + ni * 8 + (lane & 3) * 2;
                float v0 = acc[mi][ni][0] + bc[ni][0];
                float v1 = acc[mi][ni][1] + bc[ni][1];
                float v2 = acc[mi][ni][2] + bc[ni][0];
                float v3 = acc[mi][ni][3] + bc[ni][1];
                *(float2*)(rowA + c0) = make_float2(v0, v1);
                *(float2*)(rowB + c0) = make_float2(v2, v3);
                if (aA) {
                    atomicMax(&pmu[jlA * CC + c0],     encf(v0 + m2row[c0]));
                    atomicMax(&pmu[jlA * CC + c0 + 1], encf(v1 + m2row[c0 + 1]));
                }
                if (aB) {
                    atomicMax(&pmu[jlB * CC + c0],     encf(v2 + m2row[c0]));
                    atomicMax(&pmu[jlB * CC + c0 + 1], encf(v3 + m2row[c0 + 1]));
                }
            }
        }
        __syncthreads();
    }

    // ---- merge block partials into the global red slab (no-return atomics) ----
    {
        unsigned* rd = g_red + ((size_t)b * NN + j0) * CC;
        for (int m = tid; m < 2048; m += 256) {
            int jl = m >> 7, c = m & 127;
            atomicMax(&rd[jl * CC + c], pmu[m]);
        }
    }

    // ---- fused final: last CTA of the (b, jt) group computes 16 output rows ----
    __threadfence();
    __syncthreads();
    int* flag = (int*)(smem + SM_ADJ);
    if (tid == 0) {
        int old = atomicAdd(&g_cnt[b * 32 + jt], 1);
        *flag = (old == 7) ? 1 : 0;
    }
    __syncthreads();
    if (*flag) {
        float* Wo  = (float*)(smem + SM_WO2);
        float* As2 = (float*)(smem + SM_AS2);
        // load w_o2 (fp32, 64 KB) into smem
        for (int m = tid; m < 4096; m += 256)
            *(float4*)(Wo + m * 4) = *(const float4*)(w_o2 + m * 4);
        // build red rows: m1g + msgg + decoded red (L2 reads for red)
        for (int m = tid; m < 512; m += 256) {
            int rr = m >> 5, kk = (m & 31) << 2;
            int row = b * NN + j0 + rr;
            float4 v = *(const float4*)(g_m1g + (size_t)row * CC + kk);
            float4 g = *(const float4*)(g_msgg + b * CC + kk);
            const unsigned* rp = g_red + (size_t)row * CC + kk;
            v.x += g.x + decf(__ldcg(rp));
            v.y += g.y + decf(__ldcg(rp + 1));
            v.z += g.z + decf(__ldcg(rp + 2));
            v.w += g.w + decf(__ldcg(rp + 3));
            *(float4*)(As2 + rr * AS_STRIDE + kk) = v;
        }
        __syncthreads();

        const int tx = tid & 15, ty = tid >> 4;     // row=ty (16), col group=tx (8 cols)
        unsigned long long acc2[4] = {0ull, 0ull, 0ull, 0ull};
        const float* a0 = As2 + ty * AS_STRIDE;
        const float* w0 = Wo + tx * 8;
#pragma unroll 4
        for (int k = 0; k < CC; k++) {
            const ulonglong2 q0 = *(const ulonglong2*)(w0 + k * CC);
            const ulonglong2 q1 = *(const ulonglong2*)(w0 + k * CC + 4);
            const unsigned long long ap = pack2(a0[k]);
            acc2[0] = fma2(ap, q0.x, acc2[0]);
            acc2[1] = fma2(ap, q0.y, acc2[1]);
            acc2[2] = fma2(ap, q1.x, acc2[2]);
            acc2[3] = fma2(ap, q1.y, acc2[3]);
        }
        const int row = b * NN + j0 + ty;
        const float* h1 = g_h1 + (size_t)row * CC + tx * 8;
        float bv[8];
        *(float4*)(bv)     = *(const float4*)(b_o2 + tx * 8);
        *(float4*)(bv + 4) = *(const float4*)(b_o2 + tx * 8 + 4);
        float v[8];
#pragma unroll
        for (int p = 0; p < 4; p++) {
            float2 f = unpack2(acc2[p]);
            v[2 * p]     = fmaxf(f.x + bv[2 * p]     + h1[2 * p],     0.0f);
            v[2 * p + 1] = fmaxf(f.y + bv[2 * p + 1] + h1[2 * p + 1], 0.0f);
        }
        float* op = out_ret + (size_t)row * CC + tx * 8;
        *(float4*)op       = make_float4(v[0], v[1], v[2], v[3]);
        *(float4*)(op + 4) = make_float4(v[4], v[5], v[6], v[7]);
    }
}

// ---------------- launch ----------------
#define SMEM_SETUP ((CC*CC + 64*AS_STRIDE) * 4)   // 99328 (64-row proj blocks)

extern "C" void kernel_launch(void* const* d_in, const int* in_sizes, int n_in,
                              void* d_out, int out_size) {
    const float* node  = (const float*)d_in[0];
    const float* edge  = (const float*)d_in[1];
    const float* graph = (const float*)d_in[2];
    const void*  adj   = d_in[3];
    // d_in[4] = hidden (unused by reference)
    const float* w_m1 = (const float*)d_in[5];
    const float* b_m1 = (const float*)d_in[6];
    const float* w_m2 = (const float*)d_in[7];
    const float* b_m2 = (const float*)d_in[8];
    const float* w_me = (const float*)d_in[9];
    const float* b_me = (const float*)d_in[10];
    const float* w_mg = (const float*)d_in[11];
    const float* b_mg = (const float*)d_in[12];
    const float* w_o1 = (const float*)d_in[13];
    const float* b_o1 = (const float*)d_in[14];
    const float* w_o2 = (const float*)d_in[15];
    const float* b_o2 = (const float*)d_in[16];

    float* out_ret = (float*)d_out;
    float* out_me  = out_ret + RET_ELEMS;

    cudaFuncSetAttribute(big_kernel,   cudaFuncAttributeMaxDynamicSharedMemorySize, SMEM_BIG_T);
    cudaFuncSetAttribute(setup_kernel, cudaFuncAttributeMaxDynamicSharedMemorySize, SMEM_SETUP);

    noop_kernel<<<1, 32>>>();                       // shim: keep big_kernel in slot 4
    setup_kernel<<<229, 256, SMEM_SETUP>>>(adj, w_me, graph, w_mg, b_mg,
                                           node, w_m1, b_m1, w_m2, b_m2, w_o1, b_o1);
    noop_kernel<<<1, 32>>>();
    big_kernel<<<dim3(32, NIB, BB), 256, SMEM_BIG_T>>>(edge, adj, b_me,
                                                       w_o2, b_o2, out_ret, out_me);
    noop_kernel<<<1, 32>>>();                       // keep total launch count at 5
}

// round 10
// speedup vs baseline: 1.0637x; 1.0637x over previous
#include <cuda_runtime.h>
#include <cuda_fp16.h>
#include <cstdint>

// Problem constants: B=4, N=512, F=FE=FG=MID=OUT=128
#define BB 4
#define NN 512
#define CC 128
#define AS_STRIDE 132
#define RET_ELEMS (BB*NN*CC)          // 262144
#define NIB 8                         // i-blocks of 64 (512/64)

// ---------------- device scratch ----------------
__device__ float g_m1g [BB*NN*CC];              // node@w1+b1 (msgg added in final)
__device__ float g_msg2[BB*NN*CC];
__device__ float g_h1  [BB*NN*CC];
__device__ float g_msgg[BB*CC];
__device__ unsigned g_red[BB*NN*CC];            // encoded running max (1 MB)
__device__ int   g_adjflag;
__device__ __half g_wf16[CC*CC];                // W [k][n] fp16

// ---------------- helpers ----------------
__device__ __forceinline__ uint32_t smem_to_u32(const void* p) {
    uint32_t a;
    asm("{ .reg .u64 t; cvta.to.shared.u64 t, %1; cvt.u32.u64 %0, t; }"
        : "=r"(a) : "l"(p));
    return a;
}
__device__ __forceinline__ void ldsm_x4(uint32_t (&r)[4], uint32_t addr) {
    asm volatile("ldmatrix.sync.aligned.m8n8.x4.shared.b16 {%0,%1,%2,%3}, [%4];"
                 : "=r"(r[0]), "=r"(r[1]), "=r"(r[2]), "=r"(r[3]) : "r"(addr));
}
__device__ __forceinline__ void ldsm_x4_t(uint32_t (&r)[4], uint32_t addr) {
    asm volatile("ldmatrix.sync.aligned.m8n8.x4.trans.shared.b16 {%0,%1,%2,%3}, [%4];"
                 : "=r"(r[0]), "=r"(r[1]), "=r"(r[2]), "=r"(r[3]) : "r"(addr));
}
__device__ __forceinline__ void mma_f16(float (&d)[4], const uint32_t (&a)[4],
                                        uint32_t b0, uint32_t b1) {
    asm volatile("mma.sync.aligned.m16n8k16.row.col.f32.f16.f16.f32 "
                 "{%0,%1,%2,%3}, {%4,%5,%6,%7}, {%8,%9}, {%0,%1,%2,%3};"
                 : "+f"(d[0]), "+f"(d[1]), "+f"(d[2]), "+f"(d[3])
                 : "r"(a[0]), "r"(a[1]), "r"(a[2]), "r"(a[3]), "r"(b0), "r"(b1));
}
// order-preserving float<->uint for atomicMax
__device__ __forceinline__ unsigned encf(float f) {
    unsigned u = __float_as_uint(f);
    return (u & 0x80000000u) ? ~u : (u | 0x80000000u);
}
__device__ __forceinline__ float decf(unsigned u) {
    return __uint_as_float((u & 0x80000000u) ? (u & 0x7FFFFFFFu) : ~u);
}
__device__ __forceinline__ unsigned long long fma2(unsigned long long a,
                                                   unsigned long long b,
                                                   unsigned long long c) {
    unsigned long long d;
    asm("fma.rn.f32x2 %0, %1, %2, %3;" : "=l"(d) : "l"(a), "l"(b), "l"(c));
    return d;
}
__device__ __forceinline__ unsigned long long pack2(float x) {
    unsigned long long d;
    asm("mov.b64 %0, {%1, %1};" : "=l"(d) : "f"(x));
    return d;
}
__device__ __forceinline__ float2 unpack2(unsigned long long v) {
    float2 f;
    asm("mov.b64 {%0, %1}, %2;" : "=f"(f.x), "=f"(f.y) : "l"(v));
    return f;
}

// 64-row fp32x2 GEMM core
__device__ __forceinline__ void gemm_core64(const float* __restrict__ As,
                                            const float* __restrict__ Ws,
                                            unsigned long long acc[4][4],
                                            int tx, int ty)
{
    const float* a0 = As + ty * 4 * AS_STRIDE;
    const float* w0 = Ws + tx * 8;
#pragma unroll 4
    for (int k = 0; k < CC; k++) {
        const ulonglong2 q0 = *(const ulonglong2*)(w0 + k * CC);
        const ulonglong2 q1 = *(const ulonglong2*)(w0 + k * CC + 4);
        const unsigned long long b0 = q0.x, b1 = q0.y, b2 = q1.x, b3 = q1.y;
#pragma unroll
        for (int r = 0; r < 4; r++) {
            const unsigned long long ap = pack2(a0[r * AS_STRIDE + k]);
            acc[r][0] = fma2(ap, b0, acc[r][0]);
            acc[r][1] = fma2(ap, b1, acc[r][1]);
            acc[r][2] = fma2(ap, b2, acc[r][2]);
            acc[r][3] = fma2(ap, b3, acc[r][3]);
        }
    }
}

// ---------------- noop: keeps launch count/order stable for profiling ----------------
__global__ void noop_kernel() {}

// ================ merged setup kernel (setup + node projections) ================
// blk 0: adj detect; 1..64: W fp16 prep; 65..68: msg_g; 69..132: g_red init;
// 133..228: proj GEMMs (96 blocks: 32 row-tiles of 64 x 3 sets)
__global__ __launch_bounds__(256) void setup_kernel(
    const void* __restrict__ adj, const float* __restrict__ w_me,
    const float* __restrict__ graph, const float* __restrict__ w_mg,
    const float* __restrict__ b_mg,
    const float* __restrict__ node,
    const float* __restrict__ w1, const float* __restrict__ bb1,
    const float* __restrict__ w2, const float* __restrict__ bb2,
    const float* __restrict__ w3, const float* __restrict__ bb3)
{
    const int blk = blockIdx.x;
    const int t = threadIdx.x;
    if (blk == 0) {
        __shared__ int cnt[3];
        if (t < 3) cnt[t] = 0;
        __syncthreads();
#pragma unroll
        for (int u = 0; u < 2; u++) {
            size_t d = (size_t)(t + 256 * u) * 513;       // batch-0 diagonal, < 1 MB
            if (((const unsigned char*)adj)[d] == 1) atomicAdd(&cnt[0], 1);
            if (((const int*)adj)[d] == 1)           atomicAdd(&cnt[1], 1);
            if (((const float*)adj)[d] == 1.0f)      atomicAdd(&cnt[2], 1);
        }
        __syncthreads();
        if (t == 0) {
            int f = 0;
            if (cnt[0] == 512) f = 0;
            else if (cnt[1] == 512) f = 1;
            else if (cnt[2] == 512) f = 2;
            g_adjflag = f;
        }
    } else if (blk <= 64) {
        int idx = (blk - 1) * 256 + t;                    // 16384 total
        g_wf16[idx] = __float2half_rn(w_me[idx]);
    } else if (blk <= 68) {
        const int b = blk - 65;
        __shared__ float gr[CC];
        if (t < CC) gr[t] = graph[b * CC + t];
        __syncthreads();
        if (t < CC) {
            float acc = b_mg[t];
#pragma unroll 8
            for (int k = 0; k < CC; k++)
                acc = fmaf(gr[k], w_mg[k * CC + t], acc);
            g_msgg[b * CC + t] = acc;
        }
    } else if (blk <= 132) {
        const unsigned NEGU = encf(-3.0e38f);
        uint4 v = make_uint4(NEGU, NEGU, NEGU, NEGU);
        uint4* dst = (uint4*)g_red + (size_t)(blk - 69) * 1024 + t * 4;
#pragma unroll
        for (int q = 0; q < 4; q++) dst[q] = v;
    } else {
        // ---- proj: blocks 133..228, 64-row tiles ----
        extern __shared__ char smem[];
        float* Ws = (float*)smem;
        float* As = Ws + CC * CC;
        const int pidx = blk - 133;
        const int y  = pidx >> 5;          // 0..2 weight set
        const int px = pidx & 31;          // row tile (64 rows)
        const int tx = t & 15, ty = t >> 4;
        const float* W    = (y == 0) ? w1  : ((y == 1) ? w2  : w3);
        const float* bias = (y == 0) ? bb1 : ((y == 1) ? bb2 : bb3);
        float* out        = (y == 0) ? g_m1g : ((y == 1) ? g_msg2 : g_h1);
        const int rbase = px * 64;

        for (int m = t; m < 4096; m += 256)
            *(float4*)(Ws + m * 4) = *(const float4*)(W + m * 4);
        for (int m = t; m < 2048; m += 256) {
            int rr = m >> 5, kk = (m & 31) << 2;
            *(float4*)(As + rr * AS_STRIDE + kk) =
                *(const float4*)(node + (size_t)(rbase + rr) * CC + kk);
        }
        __syncthreads();

        unsigned long long acc[4][4];
#pragma unroll
        for (int r = 0; r < 4; r++)
#pragma unroll
            for (int p = 0; p < 4; p++) acc[r][p] = 0ull;
        gemm_core64(As, Ws, acc, tx, ty);

        float addv[8];
        *(float4*)(addv)     = *(const float4*)(bias + tx * 8);
        *(float4*)(addv + 4) = *(const float4*)(bias + tx * 8 + 4);
#pragma unroll
        for (int r = 0; r < 4; r++) {
            int row = rbase + ty * 4 + r;
            float v[8];
#pragma unroll
            for (int p = 0; p < 4; p++) {
                float2 f = unpack2(acc[r][p]);
                v[2 * p]     = f.x + addv[2 * p];
                v[2 * p + 1] = f.y + addv[2 * p + 1];
            }
            float* op = out + (size_t)row * CC + tx * 8;
            *(float4*)op       = make_float4(v[0], v[1], v[2], v[3]);
            *(float4*)(op + 4) = make_float4(v[4], v[5], v[6], v[7]);
        }
    }
}

// ======== big fused kernel: single-pass fp16 HMMA GEMM + masked max, 2 CTAs/SM ========
// grid (32 j-tiles of 16, 8 i-blocks of 64, 4 batches), 256 threads (8 warps 2Mx4N).
#define ROWSTRIDE 272                 // (128+8)*2 bytes, conflict-free LDSM
#define SM_W    0                     // 128 x 272 fp16 W image (34816)
#define SM_A    (SM_W   + 128*ROWSTRIDE)      // 128 x 272 fp16 A image
#define SM_MSG2 (SM_A   + 128*ROWSTRIDE)      // 64 x 128 fp32 = 32768
#define SM_PMU  (SM_MSG2 + 64*CC*4)           // 16 x 128 uint = 8192
#define SM_ADJ  (SM_PMU + 16*CC*4)            // 64 x 16 = 1024
#define SM_BIAS (SM_ADJ + 1024)               // 128 fp32
#define SMEM_BIG_T (SM_BIAS + 512)            // 112,128 bytes -> 2 CTAs/SM

__global__ __launch_bounds__(256, 2) void big_kernel(
    const float* __restrict__ edge, const void* __restrict__ adj,
    const float* __restrict__ b_me, float* __restrict__ out_me)
{
    extern __shared__ char smem[];
    const int tid  = threadIdx.x;
    const int lane = tid & 31;
    const int wid  = tid >> 5;
    const int warp_m = wid >> 2;      // 0..1  (64 rows each)
    const int warp_n = wid & 3;       // 0..3  (32 cols each)
    const int jt = blockIdx.x, iblk = blockIdx.y, b = blockIdx.z;
    const int j0 = jt * 16, ibase = iblk * 64;
    const uint32_t sb = smem_to_u32(smem);

    // ---- resident loads ----
    {
        for (int m = tid; m < 2048; m += 256) {            // W fp16 padded image
            int row = m >> 4, q = m & 15;
            *(uint4*)(smem + SM_W + row * ROWSTRIDE + q * 16) =
                ((const uint4*)g_wf16)[row * 16 + q];
        }
        const float4* m2src = (const float4*)(g_msg2 + (((size_t)b * NN + ibase) * CC));
        float4* m2dst = (float4*)(smem + SM_MSG2);
#pragma unroll
        for (int q = 0; q < 8; q++) m2dst[tid + 256 * q] = m2src[tid + 256 * q];

        if (tid < 64) {
            const int flag = g_adjflag;
            const size_t rowoff = (((size_t)b * NN) + ibase + tid) * NN + j0;
            unsigned char* dst = (unsigned char*)(smem + SM_ADJ) + tid * 16;
            if (flag == 0) {
                *(uint4*)dst = *(const uint4*)((const unsigned char*)adj + rowoff);
            } else if (flag == 1) {
                const int* p = (const int*)adj + rowoff;
#pragma unroll
                for (int q = 0; q < 16; q++) dst[q] = (p[q] != 0);
            } else {
                const float* p = (const float*)adj + rowoff;
#pragma unroll
                for (int q = 0; q < 16; q++) dst[q] = (p[q] != 0.0f);
            }
        }
        if (tid < 128) ((float*)(smem + SM_BIAS))[tid] = b_me[tid];
        const unsigned NEGU = encf(-3.0e38f);
        for (int m = tid; m < 2048; m += 256) ((unsigned*)(smem + SM_PMU))[m] = NEGU;
    }

    const float* m2S = (const float*)(smem + SM_MSG2);
    const unsigned char* adjS = (const unsigned char*)(smem + SM_ADJ);
    unsigned* pmu = (unsigned*)(smem + SM_PMU);

    const uint32_t lm_off = (uint32_t)((lane & 15) * ROWSTRIDE + (lane >> 4) * 16);
    const uint32_t a_warp = (uint32_t)(warp_m * 64 * ROWSTRIDE);
    const uint32_t b_warp = (uint32_t)(warp_n * 64);   // 32 cols * 2B

    const int jlA = lane >> 2, jlB = jlA + 8;
    float bc[4][2];
#pragma unroll
    for (int ni = 0; ni < 4; ni++) {
        int c0 = warp_n * 32 + ni * 8 + (lane & 3) * 2;
        bc[ni][0] = b_me[c0]; bc[ni][1] = b_me[c0 + 1];
    }
    __syncthreads();

    float4 ld[4];   // quarter prefetch of next sub-tile

    for (int sub = 0; sub < 8; sub++) {
        const float4* ebase = (const float4*)(edge +
            (((size_t)b * NN + ibase + sub * 8) * NN + j0) * CC);
        const int it0 = (sub == 0) ? 0 : 4;
        if (sub > 0) {
#pragma unroll
            for (int it = 0; it < 4; it++) {
                int m = tid + it * 256;
                int row = m >> 5, c4 = m & 31;
                float4 f = ld[it];
                __half2 hp0(__float2half_rn(f.x), __float2half_rn(f.y));
                __half2 hp1(__float2half_rn(f.z), __float2half_rn(f.w));
                *(uint2*)(smem + SM_A + row * ROWSTRIDE + c4 * 8) =
                    make_uint2(*(uint32_t*)&hp0, *(uint32_t*)&hp1);
            }
        }
#pragma unroll 4
        for (int it = it0; it < 16; it++) {
            int m = tid + it * 256;
            int row = m >> 5, c4 = m & 31;       // row = il*16+jl
            int il = row >> 4, jl = row & 15;
            float4 f = __ldcs(&ebase[((size_t)il * NN + jl) * 32 + c4]);   // stream
            __half2 hp0(__float2half_rn(f.x), __float2half_rn(f.y));
            __half2 hp1(__float2half_rn(f.z), __float2half_rn(f.w));
            *(uint2*)(smem + SM_A + row * ROWSTRIDE + c4 * 8) =
                make_uint2(*(uint32_t*)&hp0, *(uint32_t*)&hp1);
        }
        __syncthreads();

        if (sub < 7) {
            const float4* enext = (const float4*)(edge +
                (((size_t)b * NN + ibase + (sub + 1) * 8) * NN + j0) * CC);
#pragma unroll
            for (int it = 0; it < 4; it++) {
                int m = tid + it * 256;
                int row = m >> 5, c4 = m & 31;
                int il = row >> 4, jl = row & 15;
                ld[it] = __ldcs(&enext[((size_t)il * NN + jl) * 32 + c4]); // stream
            }
        }

        // ---- single-pass fp16 HMMA ----
        float acc[4][4][4];
#pragma unroll
        for (int mi = 0; mi < 4; mi++)
#pragma unroll
            for (int ni = 0; ni < 4; ni++)
#pragma unroll
                for (int q = 0; q < 4; q++) acc[mi][ni][q] = 0.0f;

        const uint32_t abase = sb + SM_A + a_warp + lm_off;
        const uint32_t bbase = sb + SM_W + b_warp + lm_off;
#pragma unroll
        for (int ks = 0; ks < 8; ks++) {
            uint32_t af[4][4];
            uint32_t bf[2][4];
#pragma unroll
            for (int mi = 0; mi < 4; mi++)
                ldsm_x4(af[mi], abase + mi * 16 * ROWSTRIDE + ks * 32);
#pragma unroll
            for (int nh = 0; nh < 2; nh++)
                ldsm_x4_t(bf[nh], bbase + ks * 16 * ROWSTRIDE + nh * 32);
#pragma unroll
            for (int mi = 0; mi < 4; mi++) {
#pragma unroll
                for (int ni = 0; ni < 4; ni++)
                    mma_f16(acc[mi][ni], af[mi],
                            bf[ni >> 1][(ni & 1) * 2], bf[ni >> 1][(ni & 1) * 2 + 1]);
            }
        }

        // ---- epilogue: bias + streaming STG + masked smem atomicMax ----
#pragma unroll
        for (int mi = 0; mi < 4; mi++) {
            const int il = warp_m * 4 + mi;
            const int ii = sub * 8 + il;
            const bool aA = adjS[ii * 16 + jlA] != 0;
            const bool aB = adjS[ii * 16 + jlB] != 0;
            const float* m2row = m2S + ii * CC;
            float* rowA = out_me + (((size_t)b * NN + ibase + ii) * NN + j0 + jlA) * CC;
            float* rowB = rowA + 8 * CC;
#pragma unroll
            for (int ni = 0; ni < 4; ni++) {
                const int c0 = warp_n * 32 + ni * 8 + (lane & 3) * 2;
                float v0 = acc[mi][ni][0] + bc[ni][0];
                float v1 = acc[mi][ni][1] + bc[ni][1];
                float v2 = acc[mi][ni][2] + bc[ni][0];
                float v3 = acc[mi][ni][3] + bc[ni][1];
                __stcs((float2*)(rowA + c0), make_float2(v0, v1));         // stream
                __stcs((float2*)(rowB + c0), make_float2(v2, v3));         // stream
                if (aA) {
                    atomicMax(&pmu[jlA * CC + c0],     encf(v0 + m2row[c0]));
                    atomicMax(&pmu[jlA * CC + c0 + 1], encf(v1 + m2row[c0 + 1]));
                }
                if (aB) {
                    atomicMax(&pmu[jlB * CC + c0],     encf(v2 + m2row[c0]));
                    atomicMax(&pmu[jlB * CC + c0 + 1], encf(v3 + m2row[c0 + 1]));
                }
            }
        }
        __syncthreads();
    }

    // ---- merge block partials into the global red slab (no-return atomics) ----
    {
        unsigned* rd = g_red + ((size_t)b * NN + j0) * CC;
        for (int m = tid; m < 2048; m += 256) {
            int jl = m >> 7, c = m & 127;
            atomicMax(&rd[jl * CC + c], pmu[m]);
        }
    }
}

// ---------------- final: red decode + msgg + h2 GEMM + relu (32 blocks x 64 rows) ----------------
__global__ __launch_bounds__(256) void final_kernel(
    const float* __restrict__ w_o2, const float* __restrict__ b_o2,
    float* __restrict__ out_ret)
{
    extern __shared__ char smem[];
    float* Ws = (float*)smem;
    float* As = Ws + CC * CC;

    const int t  = threadIdx.x;
    const int tx = t & 15, ty = t >> 4;
    const int rbase = blockIdx.x * 64;

    for (int m = t; m < 4096; m += 256)
        *(float4*)(Ws + m * 4) = *(const float4*)(w_o2 + m * 4);
    for (int m = t; m < 2048; m += 256) {
        int rr = m >> 5, kk = (m & 31) << 2;
        int row = rbase + rr;
        int b = row >> 9;
        float4 v = *(const float4*)(g_m1g + (size_t)row * CC + kk);
        float4 g = *(const float4*)(g_msgg + b * CC + kk);
        uint4 u = *(const uint4*)(g_red + (size_t)row * CC + kk);
        v.x += g.x + decf(u.x); v.y += g.y + decf(u.y);
        v.z += g.z + decf(u.z); v.w += g.w + decf(u.w);
        *(float4*)(As + rr * AS_STRIDE + kk) = v;
    }
    __syncthreads();

    unsigned long long acc[4][4];
#pragma unroll
    for (int r = 0; r < 4; r++)
#pragma unroll
        for (int p = 0; p < 4; p++) acc[r][p] = 0ull;
    gemm_core64(As, Ws, acc, tx, ty);

    float bv[8];
    *(float4*)(bv)     = *(const float4*)(b_o2 + tx * 8);
    *(float4*)(bv + 4) = *(const float4*)(b_o2 + tx * 8 + 4);
#pragma unroll
    for (int r = 0; r < 4; r++) {
        int row = rbase + ty * 4 + r;
        const float* h1 = g_h1 + (size_t)row * CC + tx * 8;
        float v[8];
#pragma unroll
        for (int p = 0; p < 4; p++) {
            float2 f = unpack2(acc[r][p]);
            v[2 * p]     = fmaxf(f.x + bv[2 * p]     + h1[2 * p],     0.0f);
            v[2 * p + 1] = fmaxf(f.y + bv[2 * p + 1] + h1[2 * p + 1], 0.0f);
        }
        float* op = out_ret + (size_t)row * CC + tx * 8;
        *(float4*)op       = make_float4(v[0], v[1], v[2], v[3]);
        *(float4*)(op + 4) = make_float4(v[4], v[5], v[6], v[7]);
    }
}

// ---------------- launch ----------------
#define SMEM_SETUP ((CC*CC + 64*AS_STRIDE) * 4)   // 99328
#define SMEM_FIN   ((CC*CC + 64*AS_STRIDE) * 4)   // 99328

extern "C" void kernel_launch(void* const* d_in, const int* in_sizes, int n_in,
                              void* d_out, int out_size) {
    const float* node  = (const float*)d_in[0];
    const float* edge  = (const float*)d_in[1];
    const float* graph = (const float*)d_in[2];
    const void*  adj   = d_in[3];
    // d_in[4] = hidden (unused by reference)
    const float* w_m1 = (const float*)d_in[5];
    const float* b_m1 = (const float*)d_in[6];
    const float* w_m2 = (const float*)d_in[7];
    const float* b_m2 = (const float*)d_in[8];
    const float* w_me = (const float*)d_in[9];
    const float* b_me = (const float*)d_in[10];
    const float* w_mg = (const float*)d_in[11];
    const float* b_mg = (const float*)d_in[12];
    const float* w_o1 = (const float*)d_in[13];
    const float* b_o1 = (const float*)d_in[14];
    const float* w_o2 = (const float*)d_in[15];
    const float* b_o2 = (const float*)d_in[16];

    float* out_ret = (float*)d_out;
    float* out_me  = out_ret + RET_ELEMS;

    cudaFuncSetAttribute(big_kernel,   cudaFuncAttributeMaxDynamicSharedMemorySize, SMEM_BIG_T);
    cudaFuncSetAttribute(setup_kernel, cudaFuncAttributeMaxDynamicSharedMemorySize, SMEM_SETUP);
    cudaFuncSetAttribute(final_kernel, cudaFuncAttributeMaxDynamicSharedMemorySize, SMEM_FIN);

    noop_kernel<<<1, 32>>>();                       // shim: keep big_kernel in slot 4
    setup_kernel<<<229, 256, SMEM_SETUP>>>(adj, w_me, graph, w_mg, b_mg,
                                           node, w_m1, b_m1, w_m2, b_m2, w_o1, b_o1);
    noop_kernel<<<1, 32>>>();
    big_kernel<<<dim3(32, NIB, BB), 256, SMEM_BIG_T>>>(edge, adj, b_me, out_me);
    final_kernel<<<32, 256, SMEM_FIN>>>(w_o2, b_o2, out_ret);
}

// round 11
// speedup vs baseline: 1.0955x; 1.0299x over previous
#include <cuda_runtime.h>
#include <cuda_fp16.h>
#include <cstdint>

// Problem constants: B=4, N=512, F=FE=FG=MID=OUT=128
#define BB 4
#define NN 512
#define CC 128
#define AS_STRIDE 132
#define RET_ELEMS (BB*NN*CC)          // 262144
#define NIB 8                         // i-blocks of 64 (512/64)

// ---------------- device scratch ----------------
__device__ float g_m1g [BB*NN*CC];              // node@w1+b1 (msgg added in final)
__device__ float g_msg2[BB*NN*CC];
__device__ float g_h1  [BB*NN*CC];
__device__ float g_msgg[BB*CC];
__device__ unsigned g_red[BB*NN*CC];            // encoded running max (1 MB)
__device__ int   g_adjflag;
__device__ __half g_wf16[CC*CC];                // W [k][n] fp16

// ---------------- helpers ----------------
__device__ __forceinline__ uint32_t smem_to_u32(const void* p) {
    uint32_t a;
    asm("{ .reg .u64 t; cvta.to.shared.u64 t, %1; cvt.u32.u64 %0, t; }"
        : "=r"(a) : "l"(p));
    return a;
}
__device__ __forceinline__ void ldsm_x4(uint32_t (&r)[4], uint32_t addr) {
    asm volatile("ldmatrix.sync.aligned.m8n8.x4.shared.b16 {%0,%1,%2,%3}, [%4];"
                 : "=r"(r[0]), "=r"(r[1]), "=r"(r[2]), "=r"(r[3]) : "r"(addr));
}
__device__ __forceinline__ void ldsm_x4_t(uint32_t (&r)[4], uint32_t addr) {
    asm volatile("ldmatrix.sync.aligned.m8n8.x4.trans.shared.b16 {%0,%1,%2,%3}, [%4];"
                 : "=r"(r[0]), "=r"(r[1]), "=r"(r[2]), "=r"(r[3]) : "r"(addr));
}
__device__ __forceinline__ void mma_f16(float (&d)[4], const uint32_t (&a)[4],
                                        uint32_t b0, uint32_t b1) {
    asm volatile("mma.sync.aligned.m16n8k16.row.col.f32.f16.f16.f32 "
                 "{%0,%1,%2,%3}, {%4,%5,%6,%7}, {%8,%9}, {%0,%1,%2,%3};"
                 : "+f"(d[0]), "+f"(d[1]), "+f"(d[2]), "+f"(d[3])
                 : "r"(a[0]), "r"(a[1]), "r"(a[2]), "r"(a[3]), "r"(b0), "r"(b1));
}
// order-preserving float<->uint for atomicMax
__device__ __forceinline__ unsigned encf(float f) {
    unsigned u = __float_as_uint(f);
    return (u & 0x80000000u) ? ~u : (u | 0x80000000u);
}
__device__ __forceinline__ float decf(unsigned u) {
    return __uint_as_float((u & 0x80000000u) ? (u & 0x7FFFFFFFu) : ~u);
}
__device__ __forceinline__ unsigned long long fma2(unsigned long long a,
                                                   unsigned long long b,
                                                   unsigned long long c) {
    unsigned long long d;
    asm("fma.rn.f32x2 %0, %1, %2, %3;" : "=l"(d) : "l"(a), "l"(b), "l"(c));
    return d;
}
__device__ __forceinline__ unsigned long long pack2(float x) {
    unsigned long long d;
    asm("mov.b64 %0, {%1, %1};" : "=l"(d) : "f"(x));
    return d;
}
__device__ __forceinline__ float2 unpack2(unsigned long long v) {
    float2 f;
    asm("mov.b64 {%0, %1}, %2;" : "=f"(f.x), "=f"(f.y) : "l"(v));
    return f;
}

// 64-row fp32x2 GEMM core (proj)
__device__ __forceinline__ void gemm_core64(const float* __restrict__ As,
                                            const float* __restrict__ Ws,
                                            unsigned long long acc[4][4],
                                            int tx, int ty)
{
    const float* a0 = As + ty * 4 * AS_STRIDE;
    const float* w0 = Ws + tx * 8;
#pragma unroll 4
    for (int k = 0; k < CC; k++) {
        const ulonglong2 q0 = *(const ulonglong2*)(w0 + k * CC);
        const ulonglong2 q1 = *(const ulonglong2*)(w0 + k * CC + 4);
        const unsigned long long b0 = q0.x, b1 = q0.y, b2 = q1.x, b3 = q1.y;
#pragma unroll
        for (int r = 0; r < 4; r++) {
            const unsigned long long ap = pack2(a0[r * AS_STRIDE + k]);
            acc[r][0] = fma2(ap, b0, acc[r][0]);
            acc[r][1] = fma2(ap, b1, acc[r][1]);
            acc[r][2] = fma2(ap, b2, acc[r][2]);
            acc[r][3] = fma2(ap, b3, acc[r][3]);
        }
    }
}

// shared 64-row proj body (used by setup msg2 blocks and big's tail blocks)
__device__ __forceinline__ void proj_body(char* smem, int t,
                                          const float* __restrict__ node,
                                          const float* __restrict__ W,
                                          const float* __restrict__ bias,
                                          float* __restrict__ out, int rbase)
{
    float* Ws = (float*)smem;
    float* As = Ws + CC * CC;
    const int tx = t & 15, ty = t >> 4;
    for (int m = t; m < 4096; m += 256)
        *(float4*)(Ws + m * 4) = *(const float4*)(W + m * 4);
    for (int m = t; m < 2048; m += 256) {
        int rr = m >> 5, kk = (m & 31) << 2;
        *(float4*)(As + rr * AS_STRIDE + kk) =
            *(const float4*)(node + (size_t)(rbase + rr) * CC + kk);
    }
    __syncthreads();

    unsigned long long acc[4][4];
#pragma unroll
    for (int r = 0; r < 4; r++)
#pragma unroll
        for (int p = 0; p < 4; p++) acc[r][p] = 0ull;
    gemm_core64(As, Ws, acc, tx, ty);

    float addv[8];
    *(float4*)(addv)     = *(const float4*)(bias + tx * 8);
    *(float4*)(addv + 4) = *(const float4*)(bias + tx * 8 + 4);
#pragma unroll
    for (int r = 0; r < 4; r++) {
        int row = rbase + ty * 4 + r;
        float v[8];
#pragma unroll
        for (int p = 0; p < 4; p++) {
            float2 f = unpack2(acc[r][p]);
            v[2 * p]     = f.x + addv[2 * p];
            v[2 * p + 1] = f.y + addv[2 * p + 1];
        }
        float* op = out + (size_t)row * CC + tx * 8;
        *(float4*)op       = make_float4(v[0], v[1], v[2], v[3]);
        *(float4*)(op + 4) = make_float4(v[4], v[5], v[6], v[7]);
    }
}

// ---------------- noop: keeps launch count/order stable for profiling ----------------
__global__ void noop_kernel() {}

// ================ setup kernel (only what big depends on) ================
// blk 0: adj detect; 1..64: W fp16 prep; 65..68: msg_g; 69..132: g_red init;
// 133..164: msg2 proj (32 blocks of 64 rows)
__global__ __launch_bounds__(256) void setup_kernel(
    const void* __restrict__ adj, const float* __restrict__ w_me,
    const float* __restrict__ graph, const float* __restrict__ w_mg,
    const float* __restrict__ b_mg,
    const float* __restrict__ node,
    const float* __restrict__ w2, const float* __restrict__ bb2)
{
    const int blk = blockIdx.x;
    const int t = threadIdx.x;
    if (blk == 0) {
        __shared__ int cnt[3];
        if (t < 3) cnt[t] = 0;
        __syncthreads();
#pragma unroll
        for (int u = 0; u < 2; u++) {
            size_t d = (size_t)(t + 256 * u) * 513;       // batch-0 diagonal, < 1 MB
            if (((const unsigned char*)adj)[d] == 1) atomicAdd(&cnt[0], 1);
            if (((const int*)adj)[d] == 1)           atomicAdd(&cnt[1], 1);
            if (((const float*)adj)[d] == 1.0f)      atomicAdd(&cnt[2], 1);
        }
        __syncthreads();
        if (t == 0) {
            int f = 0;
            if (cnt[0] == 512) f = 0;
            else if (cnt[1] == 512) f = 1;
            else if (cnt[2] == 512) f = 2;
            g_adjflag = f;
        }
    } else if (blk <= 64) {
        int idx = (blk - 1) * 256 + t;                    // 16384 total
        g_wf16[idx] = __float2half_rn(w_me[idx]);
    } else if (blk <= 68) {
        const int b = blk - 65;
        __shared__ float gr[CC];
        if (t < CC) gr[t] = graph[b * CC + t];
        __syncthreads();
        if (t < CC) {
            float acc = b_mg[t];
#pragma unroll 8
            for (int k = 0; k < CC; k++)
                acc = fmaf(gr[k], w_mg[k * CC + t], acc);
            g_msgg[b * CC + t] = acc;
        }
    } else if (blk <= 132) {
        const unsigned NEGU = encf(-3.0e38f);
        uint4 v = make_uint4(NEGU, NEGU, NEGU, NEGU);
        uint4* dst = (uint4*)g_red + (size_t)(blk - 69) * 1024 + t * 4;
#pragma unroll
        for (int q = 0; q < 4; q++) dst[q] = v;
    } else {
        extern __shared__ char smem[];
        proj_body(smem, t, node, w2, bb2, g_msg2, (blk - 133) * 64);
    }
}

// ======== big kernel: fp16 HMMA GEMM + masked max (blocks 0..1023),
//          plus tail proj blocks for m1g/h1 (blocks 1024..1087) ========
#define ROWSTRIDE 272                 // (128+8)*2 bytes, conflict-free LDSM
#define SM_W    0                     // 128 x 272 fp16 W image (34816)
#define SM_A    (SM_W   + 128*ROWSTRIDE)      // 128 x 272 fp16 A image
#define SM_MSG2 (SM_A   + 128*ROWSTRIDE)      // 64 x 128 fp32 = 32768
#define SM_PMU  (SM_MSG2 + 64*CC*4)           // 16 x 128 uint = 8192
#define SM_ADJ  (SM_PMU + 16*CC*4)            // 64 x 16 = 1024
#define SM_BIAS (SM_ADJ + 1024)               // 128 fp32
#define SMEM_BIG_T (SM_BIAS + 512)            // 112,128 bytes -> 2 CTAs/SM

__global__ __launch_bounds__(256, 2) void big_kernel(
    const float* __restrict__ edge, const void* __restrict__ adj,
    const float* __restrict__ b_me, float* __restrict__ out_me,
    const float* __restrict__ node,
    const float* __restrict__ w1, const float* __restrict__ bb1,
    const float* __restrict__ w3, const float* __restrict__ bb3)
{
    extern __shared__ char smem[];
    const int bx  = blockIdx.x;
    const int tid = threadIdx.x;

    // ---- tail proj blocks: m1g (0..31), h1 (32..63) ----
    if (bx >= 1024) {
        const int pidx = bx - 1024;
        const int y = pidx >> 5, px = pidx & 31;
        proj_body(smem, tid,
                  node,
                  y ? w3 : w1, y ? bb3 : bb1,
                  y ? g_h1 : g_m1g, px * 64);
        return;
    }

    const int lane = tid & 31;
    const int wid  = tid >> 5;
    const int warp_m = wid >> 2;      // 0..1  (64 rows each)
    const int warp_n = wid & 3;       // 0..3  (32 cols each)
    const int jt = bx & 31, iblk = (bx >> 5) & 7, b = bx >> 8;
    const int j0 = jt * 16, ibase = iblk * 64;
    const uint32_t sb = smem_to_u32(smem);

    // ---- resident loads ----
    {
        for (int m = tid; m < 2048; m += 256) {            // W fp16 padded image
            int row = m >> 4, q = m & 15;
            *(uint4*)(smem + SM_W + row * ROWSTRIDE + q * 16) =
                ((const uint4*)g_wf16)[row * 16 + q];
        }
        const float4* m2src = (const float4*)(g_msg2 + (((size_t)b * NN + ibase) * CC));
        float4* m2dst = (float4*)(smem + SM_MSG2);
#pragma unroll
        for (int q = 0; q < 8; q++) m2dst[tid + 256 * q] = m2src[tid + 256 * q];

        if (tid < 64) {
            const int flag = g_adjflag;
            const size_t rowoff = (((size_t)b * NN) + ibase + tid) * NN + j0;
            unsigned char* dst = (unsigned char*)(smem + SM_ADJ) + tid * 16;
            if (flag == 0) {
                *(uint4*)dst = *(const uint4*)((const unsigned char*)adj + rowoff);
            } else if (flag == 1) {
                const int* p = (const int*)adj + rowoff;
#pragma unroll
                for (int q = 0; q < 16; q++) dst[q] = (p[q] != 0);
            } else {
                const float* p = (const float*)adj + rowoff;
#pragma unroll
                for (int q = 0; q < 16; q++) dst[q] = (p[q] != 0.0f);
            }
        }
        if (tid < 128) ((float*)(smem + SM_BIAS))[tid] = b_me[tid];
        const unsigned NEGU = encf(-3.0e38f);
        for (int m = tid; m < 2048; m += 256) ((unsigned*)(smem + SM_PMU))[m] = NEGU;
    }

    const float* m2S = (const float*)(smem + SM_MSG2);
    const unsigned char* adjS = (const unsigned char*)(smem + SM_ADJ);
    unsigned* pmu = (unsigned*)(smem + SM_PMU);

    const uint32_t lm_off = (uint32_t)((lane & 15) * ROWSTRIDE + (lane >> 4) * 16);
    const uint32_t a_warp = (uint32_t)(warp_m * 64 * ROWSTRIDE);
    const uint32_t b_warp = (uint32_t)(warp_n * 64);   // 32 cols * 2B

    const int jlA = lane >> 2, jlB = jlA + 8;
    float bc[4][2];
#pragma unroll
    for (int ni = 0; ni < 4; ni++) {
        int c0 = warp_n * 32 + ni * 8 + (lane & 3) * 2;
        bc[ni][0] = b_me[c0]; bc[ni][1] = b_me[c0 + 1];
    }
    __syncthreads();

    float4 ld[4];   // quarter prefetch of next sub-tile

    for (int sub = 0; sub < 8; sub++) {
        const float4* ebase = (const float4*)(edge +
            (((size_t)b * NN + ibase + sub * 8) * NN + j0) * CC);
        const int it0 = (sub == 0) ? 0 : 4;
        if (sub > 0) {
#pragma unroll
            for (int it = 0; it < 4; it++) {
                int m = tid + it * 256;
                int row = m >> 5, c4 = m & 31;
                float4 f = ld[it];
                __half2 hp0(__float2half_rn(f.x), __float2half_rn(f.y));
                __half2 hp1(__float2half_rn(f.z), __float2half_rn(f.w));
                *(uint2*)(smem + SM_A + row * ROWSTRIDE + c4 * 8) =
                    make_uint2(*(uint32_t*)&hp0, *(uint32_t*)&hp1);
            }
        }
#pragma unroll 4
        for (int it = it0; it < 16; it++) {
            int m = tid + it * 256;
            int row = m >> 5, c4 = m & 31;       // row = il*16+jl
            int il = row >> 4, jl = row & 15;
            float4 f = __ldcs(&ebase[((size_t)il * NN + jl) * 32 + c4]);   // stream
            __half2 hp0(__float2half_rn(f.x), __float2half_rn(f.y));
            __half2 hp1(__float2half_rn(f.z), __float2half_rn(f.w));
            *(uint2*)(smem + SM_A + row * ROWSTRIDE + c4 * 8) =
                make_uint2(*(uint32_t*)&hp0, *(uint32_t*)&hp1);
        }
        __syncthreads();

        if (sub < 7) {
            const float4* enext = (const float4*)(edge +
                (((size_t)b * NN + ibase + (sub + 1) * 8) * NN + j0) * CC);
#pragma unroll
            for (int it = 0; it < 4; it++) {
                int m = tid + it * 256;
                int row = m >> 5, c4 = m & 31;
                int il = row >> 4, jl = row & 15;
                ld[it] = __ldcs(&enext[((size_t)il * NN + jl) * 32 + c4]); // stream
            }
        }

        // ---- single-pass fp16 HMMA ----
        float acc[4][4][4];
#pragma unroll
        for (int mi = 0; mi < 4; mi++)
#pragma unroll
            for (int ni = 0; ni < 4; ni++)
#pragma unroll
                for (int q = 0; q < 4; q++) acc[mi][ni][q] = 0.0f;

        const uint32_t abase = sb + SM_A + a_warp + lm_off;
        const uint32_t bbase = sb + SM_W + b_warp + lm_off;
#pragma unroll
        for (int ks = 0; ks < 8; ks++) {
            uint32_t af[4][4];
            uint32_t bf[2][4];
#pragma unroll
            for (int mi = 0; mi < 4; mi++)
                ldsm_x4(af[mi], abase + mi * 16 * ROWSTRIDE + ks * 32);
#pragma unroll
            for (int nh = 0; nh < 2; nh++)
                ldsm_x4_t(bf[nh], bbase + ks * 16 * ROWSTRIDE + nh * 32);
#pragma unroll
            for (int mi = 0; mi < 4; mi++) {
#pragma unroll
                for (int ni = 0; ni < 4; ni++)
                    mma_f16(acc[mi][ni], af[mi],
                            bf[ni >> 1][(ni & 1) * 2], bf[ni >> 1][(ni & 1) * 2 + 1]);
            }
        }

        // ---- epilogue: bias + streaming STG + masked smem atomicMax ----
#pragma unroll
        for (int mi = 0; mi < 4; mi++) {
            const int il = warp_m * 4 + mi;
            const int ii = sub * 8 + il;
            const bool aA = adjS[ii * 16 + jlA] != 0;
            const bool aB = adjS[ii * 16 + jlB] != 0;
            const float* m2row = m2S + ii * CC;
            float* rowA = out_me + (((size_t)b * NN + ibase + ii) * NN + j0 + jlA) * CC;
            float* rowB = rowA + 8 * CC;
#pragma unroll
            for (int ni = 0; ni < 4; ni++) {
                const int c0 = warp_n * 32 + ni * 8 + (lane & 3) * 2;
                float v0 = acc[mi][ni][0] + bc[ni][0];
                float v1 = acc[mi][ni][1] + bc[ni][1];
                float v2 = acc[mi][ni][2] + bc[ni][0];
                float v3 = acc[mi][ni][3] + bc[ni][1];
                __stcs((float2*)(rowA + c0), make_float2(v0, v1));         // stream
                __stcs((float2*)(rowB + c0), make_float2(v2, v3));         // stream
                if (aA) {
                    atomicMax(&pmu[jlA * CC + c0],     encf(v0 + m2row[c0]));
                    atomicMax(&pmu[jlA * CC + c0 + 1], encf(v1 + m2row[c0 + 1]));
                }
                if (aB) {
                    atomicMax(&pmu[jlB * CC + c0],     encf(v2 + m2row[c0]));
                    atomicMax(&pmu[jlB * CC + c0 + 1], encf(v3 + m2row[c0 + 1]));
                }
            }
        }
        __syncthreads();
    }

    // ---- merge block partials into the global red slab (no-return atomics) ----
    {
        unsigned* rd = g_red + ((size_t)b * NN + j0) * CC;
        for (int m = tid; m < 2048; m += 256) {
            int jl = m >> 7, c = m & 127;
            atomicMax(&rd[jl * CC + c], pmu[m]);
        }
    }
}

// ---------------- final: red decode + msgg + h2 GEMM + relu (64 blocks x 32 rows) ----------------
__global__ __launch_bounds__(256) void final_kernel(
    const float* __restrict__ w_o2, const float* __restrict__ b_o2,
    float* __restrict__ out_ret)
{
    extern __shared__ char smem[];
    float* Ws = (float*)smem;
    float* As = Ws + CC * CC;

    const int t  = threadIdx.x;
    const int tx = t & 15, ty = t >> 4;
    const int rbase = blockIdx.x * 32;

    for (int m = t; m < 4096; m += 256)
        *(float4*)(Ws + m * 4) = *(const float4*)(w_o2 + m * 4);
    for (int m = t; m < 1024; m += 256) {
        int rr = m >> 5, kk = (m & 31) << 2;
        int row = rbase + rr;
        int b = row >> 9;
        float4 v = *(const float4*)(g_m1g + (size_t)row * CC + kk);
        float4 g = *(const float4*)(g_msgg + b * CC + kk);
        uint4 u = *(const uint4*)(g_red + (size_t)row * CC + kk);
        v.x += g.x + decf(u.x); v.y += g.y + decf(u.y);
        v.z += g.z + decf(u.z); v.w += g.w + decf(u.w);
        *(float4*)(As + rr * AS_STRIDE + kk) = v;
    }
    __syncthreads();

    // 32-row GEMM: each thread does rows ty*2 .. ty*2+1
    unsigned long long acc[2][4];
#pragma unroll
    for (int r = 0; r < 2; r++)
#pragma unroll
        for (int p = 0; p < 4; p++) acc[r][p] = 0ull;
    {
        const float* a0 = As + ty * 2 * AS_STRIDE;
        const float* w0 = Ws + tx * 8;
#pragma unroll 4
        for (int k = 0; k < CC; k++) {
            const ulonglong2 q0 = *(const ulonglong2*)(w0 + k * CC);
            const ulonglong2 q1 = *(const ulonglong2*)(w0 + k * CC + 4);
#pragma unroll
            for (int r = 0; r < 2; r++) {
                const unsigned long long ap = pack2(a0[r * AS_STRIDE + k]);
                acc[r][0] = fma2(ap, q0.x, acc[r][0]);
                acc[r][1] = fma2(ap, q0.y, acc[r][1]);
                acc[r][2] = fma2(ap, q1.x, acc[r][2]);
                acc[r][3] = fma2(ap, q1.y, acc[r][3]);
            }
        }
    }

    float bv[8];
    *(float4*)(bv)     = *(const float4*)(b_o2 + tx * 8);
    *(float4*)(bv + 4) = *(const float4*)(b_o2 + tx * 8 + 4);
#pragma unroll
    for (int r = 0; r < 2; r++) {
        int row = rbase + ty * 2 + r;
        const float* h1 = g_h1 + (size_t)row * CC + tx * 8;
        float v[8];
#pragma unroll
        for (int p = 0; p < 4; p++) {
            float2 f = unpack2(acc[r][p]);
            v[2 * p]     = fmaxf(f.x + bv[2 * p]     + h1[2 * p],     0.0f);
            v[2 * p + 1] = fmaxf(f.y + bv[2 * p + 1] + h1[2 * p + 1], 0.0f);
        }
        float* op = out_ret + (size_t)row * CC + tx * 8;
        *(float4*)op       = make_float4(v[0], v[1], v[2], v[3]);
        *(float4*)(op + 4) = make_float4(v[4], v[5], v[6], v[7]);
    }
}

// ---------------- launch ----------------
#define SMEM_SETUP ((CC*CC + 64*AS_STRIDE) * 4)   // 99328
#define SMEM_FIN   ((CC*CC + 32*AS_STRIDE) * 4)   // 82432

extern "C" void kernel_launch(void* const* d_in, const int* in_sizes, int n_in,
                              void* d_out, int out_size) {
    const float* node  = (const float*)d_in[0];
    const float* edge  = (const float*)d_in[1];
    const float* graph = (const float*)d_in[2];
    const void*  adj   = d_in[3];
    // d_in[4] = hidden (unused by reference)
    const float* w_m1 = (const float*)d_in[5];
    const float* b_m1 = (const float*)d_in[6];
    const float* w_m2 = (const float*)d_in[7];
    const float* b_m2 = (const float*)d_in[8];
    const float* w_me = (const float*)d_in[9];
    const float* b_me = (const float*)d_in[10];
    const float* w_mg = (const float*)d_in[11];
    const float* b_mg = (const float*)d_in[12];
    const float* w_o1 = (const float*)d_in[13];
    const float* b_o1 = (const float*)d_in[14];
    const float* w_o2 = (const float*)d_in[15];
    const float* b_o2 = (const float*)d_in[16];

    float* out_ret = (float*)d_out;
    float* out_me  = out_ret + RET_ELEMS;

    cudaFuncSetAttribute(big_kernel,   cudaFuncAttributeMaxDynamicSharedMemorySize, SMEM_BIG_T);
    cudaFuncSetAttribute(setup_kernel, cudaFuncAttributeMaxDynamicSharedMemorySize, SMEM_SETUP);
    cudaFuncSetAttribute(final_kernel, cudaFuncAttributeMaxDynamicSharedMemorySize, SMEM_FIN);

    noop_kernel<<<1, 32>>>();                       // shim: keep big_kernel in slot 4
    setup_kernel<<<165, 256, SMEM_SETUP>>>(adj, w_me, graph, w_mg, b_mg,
                                           node, w_m2, b_m2);
    noop_kernel<<<1, 32>>>();
    big_kernel<<<1088, 256, SMEM_BIG_T>>>(edge, adj, b_me, out_me,
                                          node, w_m1, b_m1, w_o1, b_o1);
    final_kernel<<<64, 256, SMEM_FIN>>>(w_o2, b_o2, out_ret);
}

// round 13
// speedup vs baseline: 1.2051x; 1.1001x over previous
#include <cuda_runtime.h>
#include <cuda_fp16.h>
#include <cstdint>

// Problem constants: B=4, N=512, F=FE=FG=MID=OUT=128
#define BB 4
#define NN 512
#define CC 128
#define AS_STRIDE 132
#define RET_ELEMS (BB*NN*CC)          // 262144
#define NIB 16                        // i-blocks of 32 (512/32)

// ---------------- device scratch ----------------
__device__ float g_m1g [BB*NN*CC];              // node@w1+b1 (msgg added in final)
__device__ float g_msg2[BB*NN*CC];
__device__ float g_h1  [BB*NN*CC];
__device__ float g_msgg[BB*CC];
__device__ unsigned g_red[BB*NN*CC];            // encoded running max (1 MB)
__device__ int   g_adjflag;
__device__ __half g_wf16[CC*CC];                // W [k][n] fp16

// ---------------- helpers ----------------
__device__ __forceinline__ uint32_t smem_to_u32(const void* p) {
    uint32_t a;
    asm("{ .reg .u64 t; cvta.to.shared.u64 t, %1; cvt.u32.u64 %0, t; }"
        : "=r"(a) : "l"(p));
    return a;
}
__device__ __forceinline__ void ldsm_x4(uint32_t (&r)[4], uint32_t addr) {
    asm volatile("ldmatrix.sync.aligned.m8n8.x4.shared.b16 {%0,%1,%2,%3}, [%4];"
                 : "=r"(r[0]), "=r"(r[1]), "=r"(r[2]), "=r"(r[3]) : "r"(addr));
}
__device__ __forceinline__ void ldsm_x4_t(uint32_t (&r)[4], uint32_t addr) {
    asm volatile("ldmatrix.sync.aligned.m8n8.x4.trans.shared.b16 {%0,%1,%2,%3}, [%4];"
                 : "=r"(r[0]), "=r"(r[1]), "=r"(r[2]), "=r"(r[3]) : "r"(addr));
}
__device__ __forceinline__ void mma_f16(float (&d)[4], const uint32_t (&a)[4],
                                        uint32_t b0, uint32_t b1) {
    asm volatile("mma.sync.aligned.m16n8k16.row.col.f32.f16.f16.f32 "
                 "{%0,%1,%2,%3}, {%4,%5,%6,%7}, {%8,%9}, {%0,%1,%2,%3};"
                 : "+f"(d[0]), "+f"(d[1]), "+f"(d[2]), "+f"(d[3])
                 : "r"(a[0]), "r"(a[1]), "r"(a[2]), "r"(a[3]), "r"(b0), "r"(b1));
}
// order-preserving float<->uint for atomicMax
__device__ __forceinline__ unsigned encf(float f) {
    unsigned u = __float_as_uint(f);
    return (u & 0x80000000u) ? ~u : (u | 0x80000000u);
}
__device__ __forceinline__ float decf(unsigned u) {
    return __uint_as_float((u & 0x80000000u) ? (u & 0x7FFFFFFFu) : ~u);
}
__device__ __forceinline__ unsigned long long fma2(unsigned long long a,
                                                   unsigned long long b,
                                                   unsigned long long c) {
    unsigned long long d;
    asm("fma.rn.f32x2 %0, %1, %2, %3;" : "=l"(d) : "l"(a), "l"(b), "l"(c));
    return d;
}
__device__ __forceinline__ unsigned long long pack2(float x) {
    unsigned long long d;
    asm("mov.b64 %0, {%1, %1};" : "=l"(d) : "f"(x));
    return d;
}
__device__ __forceinline__ float2 unpack2(unsigned long long v) {
    float2 f;
    asm("mov.b64 {%0, %1}, %2;" : "=f"(f.x), "=f"(f.y) : "l"(v));
    return f;
}

// 64-row fp32x2 GEMM core (proj)
__device__ __forceinline__ void gemm_core64(const float* __restrict__ As,
                                            const float* __restrict__ Ws,
                                            unsigned long long acc[4][4],
                                            int tx, int ty)
{
    const float* a0 = As + ty * 4 * AS_STRIDE;
    const float* w0 = Ws + tx * 8;
#pragma unroll 4
    for (int k = 0; k < CC; k++) {
        const ulonglong2 q0 = *(const ulonglong2*)(w0 + k * CC);
        const ulonglong2 q1 = *(const ulonglong2*)(w0 + k * CC + 4);
        const unsigned long long b0 = q0.x, b1 = q0.y, b2 = q1.x, b3 = q1.y;
#pragma unroll
        for (int r = 0; r < 4; r++) {
            const unsigned long long ap = pack2(a0[r * AS_STRIDE + k]);
            acc[r][0] = fma2(ap, b0, acc[r][0]);
            acc[r][1] = fma2(ap, b1, acc[r][1]);
            acc[r][2] = fma2(ap, b2, acc[r][2]);
            acc[r][3] = fma2(ap, b3, acc[r][3]);
        }
    }
}

// shared 64-row proj body (needs CC*CC*4 + 64*AS_STRIDE*4 = 99328 bytes smem)
__device__ __forceinline__ void proj_body(char* smem, int t,
                                          const float* __restrict__ node,
                                          const float* __restrict__ W,
                                          const float* __restrict__ bias,
                                          float* __restrict__ out, int rbase)
{
    float* Ws = (float*)smem;
    float* As = Ws + CC * CC;
    const int tx = t & 15, ty = t >> 4;
    for (int m = t; m < 4096; m += 256)
        *(float4*)(Ws + m * 4) = *(const float4*)(W + m * 4);
    for (int m = t; m < 2048; m += 256) {
        int rr = m >> 5, kk = (m & 31) << 2;
        *(float4*)(As + rr * AS_STRIDE + kk) =
            *(const float4*)(node + (size_t)(rbase + rr) * CC + kk);
    }
    __syncthreads();

    unsigned long long acc[4][4];
#pragma unroll
    for (int r = 0; r < 4; r++)
#pragma unroll
        for (int p = 0; p < 4; p++) acc[r][p] = 0ull;
    gemm_core64(As, Ws, acc, tx, ty);

    float addv[8];
    *(float4*)(addv)     = *(const float4*)(bias + tx * 8);
    *(float4*)(addv + 4) = *(const float4*)(bias + tx * 8 + 4);
#pragma unroll
    for (int r = 0; r < 4; r++) {
        int row = rbase + ty * 4 + r;
        float v[8];
#pragma unroll
        for (int p = 0; p < 4; p++) {
            float2 f = unpack2(acc[r][p]);
            v[2 * p]     = f.x + addv[2 * p];
            v[2 * p + 1] = f.y + addv[2 * p + 1];
        }
        float* op = out + (size_t)row * CC + tx * 8;
        *(float4*)op       = make_float4(v[0], v[1], v[2], v[3]);
        *(float4*)(op + 4) = make_float4(v[4], v[5], v[6], v[7]);
    }
}

// ---------------- noop: keeps launch count/order stable for profiling ----------------
__global__ void noop_kernel() {}

// ================ setup kernel (only what big depends on) ================
// blk 0: adj detect; 1..64: W fp16 prep; 65..68: msg_g; 69..132: g_red init;
// 133..164: msg2 proj (32 blocks of 64 rows)
__global__ __launch_bounds__(256) void setup_kernel(
    const void* __restrict__ adj, const float* __restrict__ w_me,
    const float* __restrict__ graph, const float* __restrict__ w_mg,
    const float* __restrict__ b_mg,
    const float* __restrict__ node,
    const float* __restrict__ w2, const float* __restrict__ bb2)
{
    const int blk = blockIdx.x;
    const int t = threadIdx.x;
    if (blk == 0) {
        __shared__ int cnt[3];
        if (t < 3) cnt[t] = 0;
        __syncthreads();
#pragma unroll
        for (int u = 0; u < 2; u++) {
            size_t d = (size_t)(t + 256 * u) * 513;       // batch-0 diagonal, < 1 MB
            if (((const unsigned char*)adj)[d] == 1) atomicAdd(&cnt[0], 1);
            if (((const int*)adj)[d] == 1)           atomicAdd(&cnt[1], 1);
            if (((const float*)adj)[d] == 1.0f)      atomicAdd(&cnt[2], 1);
        }
        __syncthreads();
        if (t == 0) {
            int f = 0;
            if (cnt[0] == 512) f = 0;
            else if (cnt[1] == 512) f = 1;
            else if (cnt[2] == 512) f = 2;
            g_adjflag = f;
        }
    } else if (blk <= 64) {
        int idx = (blk - 1) * 256 + t;                    // 16384 total
        g_wf16[idx] = __float2half_rn(w_me[idx]);
    } else if (blk <= 68) {
        const int b = blk - 65;
        __shared__ float gr[CC];
        if (t < CC) gr[t] = graph[b * CC + t];
        __syncthreads();
        if (t < CC) {
            float acc = b_mg[t];
#pragma unroll 8
            for (int k = 0; k < CC; k++)
                acc = fmaf(gr[k], w_mg[k * CC + t], acc);
            g_msgg[b * CC + t] = acc;
        }
    } else if (blk <= 132) {
        const unsigned NEGU = encf(-3.0e38f);
        uint4 v = make_uint4(NEGU, NEGU, NEGU, NEGU);
        uint4* dst = (uint4*)g_red + (size_t)(blk - 69) * 1024 + t * 4;
#pragma unroll
        for (int q = 0; q < 4; q++) dst[q] = v;
    } else {
        extern __shared__ char smem[];
        proj_body(smem, t, node, w2, bb2, g_msg2, (blk - 133) * 64);
    }
}

// ======== big kernel: fp16 HMMA GEMM + masked max (blocks 0..2047, i-blocks of 32),
//          plus tail proj blocks for m1g/h1 (blocks 2048..2111) ========
#define ROWSTRIDE 272                 // (128+8)*2 bytes, conflict-free LDSM
#define SM_W    0                     // 128 x 272 fp16 W image (34816)
#define SM_A    (SM_W   + 128*ROWSTRIDE)      // 128 x 272 fp16 A image (34816)
#define SM_MSG2 (SM_A   + 128*ROWSTRIDE)      // 32 x 128 fp32 = 16384
#define SM_PMU  (SM_MSG2 + 32*CC*4)           // 16 x 128 uint = 8192
#define SM_ADJ  (SM_PMU + 16*CC*4)            // 32 x 16 = 512
#define SM_BIAS (SM_ADJ + 512)                // 128 fp32
// allocation must also cover proj_body's 99,328-byte layout:
#define SMEM_BIG_T 99328                      // 2 x 99328 = 198656 B/SM -> 2 CTAs/SM

__global__ __launch_bounds__(256, 2) void big_kernel(
    const float* __restrict__ edge, const void* __restrict__ adj,
    const float* __restrict__ b_me, float* __restrict__ out_me,
    const float* __restrict__ node,
    const float* __restrict__ w1, const float* __restrict__ bb1,
    const float* __restrict__ w3, const float* __restrict__ bb3)
{
    extern __shared__ char smem[];
    const int bx  = blockIdx.x;
    const int tid = threadIdx.x;

    // ---- tail proj blocks: m1g (0..31), h1 (32..63) ----
    if (bx >= 2048) {
        const int pidx = bx - 2048;
        const int y = pidx >> 5, px = pidx & 31;
        proj_body(smem, tid,
                  node,
                  y ? w3 : w1, y ? bb3 : bb1,
                  y ? g_h1 : g_m1g, px * 64);
        return;
    }

    const int lane = tid & 31;
    const int wid  = tid >> 5;
    const int warp_m = wid >> 2;      // 0..1  (64 rows each)
    const int warp_n = wid & 3;       // 0..3  (32 cols each)
    const int jt = bx & 31, iblk = (bx >> 5) & 15, b = bx >> 9;
    const int j0 = jt * 16, ibase = iblk * 32;
    const uint32_t sb = smem_to_u32(smem);

    // ---- resident loads ----
    {
        for (int m = tid; m < 2048; m += 256) {            // W fp16 padded image
            int row = m >> 4, q = m & 15;
            *(uint4*)(smem + SM_W + row * ROWSTRIDE + q * 16) =
                ((const uint4*)g_wf16)[row * 16 + q];
        }
        const float4* m2src = (const float4*)(g_msg2 + (((size_t)b * NN + ibase) * CC));
        float4* m2dst = (float4*)(smem + SM_MSG2);
#pragma unroll
        for (int q = 0; q < 4; q++) m2dst[tid + 256 * q] = m2src[tid + 256 * q];

        if (tid < 32) {
            const int flag = g_adjflag;
            const size_t rowoff = (((size_t)b * NN) + ibase + tid) * NN + j0;
            unsigned char* dst = (unsigned char*)(smem + SM_ADJ) + tid * 16;
            if (flag == 0) {
                *(uint4*)dst = *(const uint4*)((const unsigned char*)adj + rowoff);
            } else if (flag == 1) {
                const int* p = (const int*)adj + rowoff;
#pragma unroll
                for (int q = 0; q < 16; q++) dst[q] = (p[q] != 0);
            } else {
                const float* p = (const float*)adj + rowoff;
#pragma unroll
                for (int q = 0; q < 16; q++) dst[q] = (p[q] != 0.0f);
            }
        }
        if (tid < 128) ((float*)(smem + SM_BIAS))[tid] = b_me[tid];
        const unsigned NEGU = encf(-3.0e38f);
        for (int m = tid; m < 2048; m += 256) ((unsigned*)(smem + SM_PMU))[m] = NEGU;
    }

    const float* m2S = (const float*)(smem + SM_MSG2);
    const unsigned char* adjS = (const unsigned char*)(smem + SM_ADJ);
    unsigned* pmu = (unsigned*)(smem + SM_PMU);

    const uint32_t lm_off = (uint32_t)((lane & 15) * ROWSTRIDE + (lane >> 4) * 16);
    const uint32_t a_warp = (uint32_t)(warp_m * 64 * ROWSTRIDE);
    const uint32_t b_warp = (uint32_t)(warp_n * 64);   // 32 cols * 2B

    const int jlA = lane >> 2, jlB = jlA + 8;
    float bc[4][2];
#pragma unroll
    for (int ni = 0; ni < 4; ni++) {
        int c0 = warp_n * 32 + ni * 8 + (lane & 3) * 2;
        bc[ni][0] = b_me[c0]; bc[ni][1] = b_me[c0 + 1];
    }
    __syncthreads();

    float4 ld[4];   // quarter prefetch of next sub-tile

    for (int sub = 0; sub < 4; sub++) {
        const float4* ebase = (const float4*)(edge +
            (((size_t)b * NN + ibase + sub * 8) * NN + j0) * CC);
        const int it0 = (sub == 0) ? 0 : 4;
        if (sub > 0) {
#pragma unroll
            for (int it = 0; it < 4; it++) {
                int m = tid + it * 256;
                int row = m >> 5, c4 = m & 31;
                float4 f = ld[it];
                __half2 hp0(__float2half_rn(f.x), __float2half_rn(f.y));
                __half2 hp1(__float2half_rn(f.z), __float2half_rn(f.w));
                *(uint2*)(smem + SM_A + row * ROWSTRIDE + c4 * 8) =
                    make_uint2(*(uint32_t*)&hp0, *(uint32_t*)&hp1);
            }
        }
#pragma unroll 4
        for (int it = it0; it < 16; it++) {
            int m = tid + it * 256;
            int row = m >> 5, c4 = m & 31;       // row = il*16+jl
            int il = row >> 4, jl = row & 15;
            float4 f = __ldcs(&ebase[((size_t)il * NN + jl) * 32 + c4]);   // stream
            __half2 hp0(__float2half_rn(f.x), __float2half_rn(f.y));
            __half2 hp1(__float2half_rn(f.z), __float2half_rn(f.w));
            *(uint2*)(smem + SM_A + row * ROWSTRIDE + c4 * 8) =
                make_uint2(*(uint32_t*)&hp0, *(uint32_t*)&hp1);
        }
        __syncthreads();

        if (sub < 3) {
            const float4* enext = (const float4*)(edge +
                (((size_t)b * NN + ibase + (sub + 1) * 8) * NN + j0) * CC);
#pragma unroll
            for (int it = 0; it < 4; it++) {
                int m = tid + it * 256;
                int row = m >> 5, c4 = m & 31;
                int il = row >> 4, jl = row & 15;
                ld[it] = __ldcs(&enext[((size_t)il * NN + jl) * 32 + c4]); // stream
            }
        }

        // ---- single-pass fp16 HMMA ----
        float acc[4][4][4];
#pragma unroll
        for (int mi = 0; mi < 4; mi++)
#pragma unroll
            for (int ni = 0; ni < 4; ni++)
#pragma unroll
                for (int q = 0; q < 4; q++) acc[mi][ni][q] = 0.0f;

        const uint32_t abase = sb + SM_A + a_warp + lm_off;
        const uint32_t bbase = sb + SM_W + b_warp + lm_off;
#pragma unroll
        for (int ks = 0; ks < 8; ks++) {
            uint32_t af[4][4];
            uint32_t bf[2][4];
#pragma unroll
            for (int mi = 0; mi < 4; mi++)
                ldsm_x4(af[mi], abase + mi * 16 * ROWSTRIDE + ks * 32);
#pragma unroll
            for (int nh = 0; nh < 2; nh++)
                ldsm_x4_t(bf[nh], bbase + ks * 16 * ROWSTRIDE + nh * 32);
#pragma unroll
            for (int mi = 0; mi < 4; mi++) {
#pragma unroll
                for (int ni = 0; ni < 4; ni++)
                    mma_f16(acc[mi][ni], af[mi],
                            bf[ni >> 1][(ni & 1) * 2], bf[ni >> 1][(ni & 1) * 2 + 1]);
            }
        }

        // ---- epilogue: bias + streaming STG + masked smem atomicMax ----
#pragma unroll
        for (int mi = 0; mi < 4; mi++) {
            const int il = warp_m * 4 + mi;
            const int ii = sub * 8 + il;
            const bool aA = adjS[ii * 16 + jlA] != 0;
            const bool aB = adjS[ii * 16 + jlB] != 0;
            const float* m2row = m2S + ii * CC;
            float* rowA = out_me + (((size_t)b * NN + ibase + ii) * NN + j0 + jlA) * CC;
            float* rowB = rowA + 8 * CC;
#pragma unroll
            for (int ni = 0; ni < 4; ni++) {
                const int c0 = warp_n * 32 + ni * 8 + (lane & 3) * 2;
                float v0 = acc[mi][ni][0] + bc[ni][0];
                float v1 = acc[mi][ni][1] + bc[ni][1];
                float v2 = acc[mi][ni][2] + bc[ni][0];
                float v3 = acc[mi][ni][3] + bc[ni][1];
                __stcs((float2*)(rowA + c0), make_float2(v0, v1));         // stream
                __stcs((float2*)(rowB + c0), make_float2(v2, v3));         // stream
                if (aA) {
                    atomicMax(&pmu[jlA * CC + c0],     encf(v0 + m2row[c0]));
                    atomicMax(&pmu[jlA * CC + c0 + 1], encf(v1 + m2row[c0 + 1]));
                }
                if (aB) {
                    atomicMax(&pmu[jlB * CC + c0],     encf(v2 + m2row[c0]));
                    atomicMax(&pmu[jlB * CC + c0 + 1], encf(v3 + m2row[c0 + 1]));
                }
            }
        }
        __syncthreads();
    }

    // ---- merge block partials into the global red slab (no-return atomics) ----
    {
        unsigned* rd = g_red + ((size_t)b * NN + j0) * CC;
        for (int m = tid; m < 2048; m += 256) {
            int jl = m >> 7, c = m & 127;
            atomicMax(&rd[jl * CC + c], pmu[m]);
        }
    }
}

// ---------------- final: red decode + msgg + h2 GEMM + relu (64 blocks x 32 rows) ----------------
__global__ __launch_bounds__(256) void final_kernel(
    const float* __restrict__ w_o2, const float* __restrict__ b_o2,
    float* __restrict__ out_ret)
{
    extern __shared__ char smem[];
    float* Ws = (float*)smem;
    float* As = Ws + CC * CC;

    const int t  = threadIdx.x;
    const int tx = t & 15, ty = t >> 4;
    const int rbase = blockIdx.x * 32;

    for (int m = t; m < 4096; m += 256)
        *(float4*)(Ws + m * 4) = *(const float4*)(w_o2 + m * 4);
    for (int m = t; m < 1024; m += 256) {
        int rr = m >> 5, kk = (m & 31) << 2;
        int row = rbase + rr;
        int b = row >> 9;
        float4 v = *(const float4*)(g_m1g + (size_t)row * CC + kk);
        float4 g = *(const float4*)(g_msgg + b * CC + kk);
        uint4 u = *(const uint4*)(g_red + (size_t)row * CC + kk);
        v.x += g.x + decf(u.x); v.y += g.y + decf(u.y);
        v.z += g.z + decf(u.z); v.w += g.w + decf(u.w);
        *(float4*)(As + rr * AS_STRIDE + kk) = v;
    }
    __syncthreads();

    unsigned long long acc[2][4];
#pragma unroll
    for (int r = 0; r < 2; r++)
#pragma unroll
        for (int p = 0; p < 4; p++) acc[r][p] = 0ull;
    {
        const float* a0 = As + ty * 2 * AS_STRIDE;
        const float* w0 = Ws + tx * 8;
#pragma unroll 4
        for (int k = 0; k < CC; k++) {
            const ulonglong2 q0 = *(const ulonglong2*)(w0 + k * CC);
            const ulonglong2 q1 = *(const ulonglong2*)(w0 + k * CC + 4);
#pragma unroll
            for (int r = 0; r < 2; r++) {
                const unsigned long long ap = pack2(a0[r * AS_STRIDE + k]);
                acc[r][0] = fma2(ap, q0.x, acc[r][0]);
                acc[r][1] = fma2(ap, q0.y, acc[r][1]);
                acc[r][2] = fma2(ap, q1.x, acc[r][2]);
                acc[r][3] = fma2(ap, q1.y, acc[r][3]);
            }
        }
    }

    float bv[8];
    *(float4*)(bv)     = *(const float4*)(b_o2 + tx * 8);
    *(float4*)(bv + 4) = *(const float4*)(b_o2 + tx * 8 + 4);
#pragma unroll
    for (int r = 0; r < 2; r++) {
        int row = rbase + ty * 2 + r;
        const float* h1 = g_h1 + (size_t)row * CC + tx * 8;
        float v[8];
#pragma unroll
        for (int p = 0; p < 4; p++) {
            float2 f = unpack2(acc[r][p]);
            v[2 * p]     = fmaxf(f.x + bv[2 * p]     + h1[2 * p],     0.0f);
            v[2 * p + 1] = fmaxf(f.y + bv[2 * p + 1] + h1[2 * p + 1], 0.0f);
        }
        float* op = out_ret + (size_t)row * CC + tx * 8;
        *(float4*)op       = make_float4(v[0], v[1], v[2], v[3]);
        *(float4*)(op + 4) = make_float4(v[4], v[5], v[6], v[7]);
    }
}

// ---------------- launch ----------------
#define SMEM_SETUP ((CC*CC + 64*AS_STRIDE) * 4)   // 99328
#define SMEM_FIN   ((CC*CC + 32*AS_STRIDE) * 4)   // 82432

extern "C" void kernel_launch(void* const* d_in, const int* in_sizes, int n_in,
                              void* d_out, int out_size) {
    const float* node  = (const float*)d_in[0];
    const float* edge  = (const float*)d_in[1];
    const float* graph = (const float*)d_in[2];
    const void*  adj   = d_in[3];
    // d_in[4] = hidden (unused by reference)
    const float* w_m1 = (const float*)d_in[5];
    const float* b_m1 = (const float*)d_in[6];
    const float* w_m2 = (const float*)d_in[7];
    const float* b_m2 = (const float*)d_in[8];
    const float* w_me = (const float*)d_in[9];
    const float* b_me = (const float*)d_in[10];
    const float* w_mg = (const float*)d_in[11];
    const float* b_mg = (const float*)d_in[12];
    const float* w_o1 = (const float*)d_in[13];
    const float* b_o1 = (const float*)d_in[14];
    const float* w_o2 = (const float*)d_in[15];
    const float* b_o2 = (const float*)d_in[16];

    float* out_ret = (float*)d_out;
    float* out_me  = out_ret + RET_ELEMS;

    cudaFuncSetAttribute(big_kernel,   cudaFuncAttributeMaxDynamicSharedMemorySize, SMEM_BIG_T);
    cudaFuncSetAttribute(setup_kernel, cudaFuncAttributeMaxDynamicSharedMemorySize, SMEM_SETUP);
    cudaFuncSetAttribute(final_kernel, cudaFuncAttributeMaxDynamicSharedMemorySize, SMEM_FIN);

    noop_kernel<<<1, 32>>>();                       // shim: keep big_kernel in slot 4
    setup_kernel<<<165, 256, SMEM_SETUP>>>(adj, w_me, graph, w_mg, b_mg,
                                           node, w_m2, b_m2);
    noop_kernel<<<1, 32>>>();
    big_kernel<<<2112, 256, SMEM_BIG_T>>>(edge, adj, b_me, out_me,
                                          node, w_m1, b_m1, w_o1, b_o1);
    final_kernel<<<64, 256, SMEM_FIN>>>(w_o2, b_o2, out_ret);
}